// round 6
// baseline (speedup 1.0000x reference)
#include <cuda_runtime.h>
#include <math.h>
#include <stddef.h>

#define Bsz 256
#define Dd  512
#define Hh  512
#define Uu  24
#define Kk  8
#define IKk 64
#define IVv 400
#define CKk 32
#define NCHh 4
#define CVv 512

// ---------------- scratch (static device globals; no allocation) ----------------
__device__ float g_k0[Bsz * IKk];
__device__ float g_v0[Bsz * IVv];
__device__ float g_s0[Bsz * Uu];
__device__ float g_p0[Bsz * Uu];
__device__ float g_mask[Bsz * Uu];
__device__ float g_inp[Bsz * Uu * IVv];
__device__ float g_pre[(size_t)Bsz * Uu * 4 * Hh];   // 50 MB
__device__ float g_ht[Bsz * Uu * Hh];
__device__ float g_ct[Bsz * Uu * Hh];
__device__ float g_qc[Bsz * Uu * NCHh * CKk];
__device__ float g_kc[Bsz * Uu * NCHh * CKk];
__device__ float g_vc[(size_t)Bsz * Uu * NCHh * CVv];  // 50 MB
__device__ float g_ctx[(size_t)Bsz * Uu * NCHh * CVv]; // 50 MB

// ---------------- stage A: k0 = x@key_w+key_b, v0 = x@value_w+value_b ----------
__global__ void kv_kernel(const float* __restrict__ x,
                          const float* __restrict__ key_w, const float* __restrict__ key_b,
                          const float* __restrict__ value_w, const float* __restrict__ value_b) {
    int b = blockIdx.x;
    __shared__ float xs[Dd];
    int tid = threadIdx.x; // 512
    xs[tid] = x[(size_t)b * Dd + tid];
    __syncthreads();
    if (tid < IVv) {
        float acc = value_b[tid];
        #pragma unroll 8
        for (int d = 0; d < Dd; d++) acc += xs[d] * value_w[(size_t)d * IVv + tid];
        g_v0[b * IVv + tid] = acc;
    } else if (tid < IVv + IKk) {
        int ik = tid - IVv;
        float acc = key_b[ik];
        #pragma unroll 8
        for (int d = 0; d < Dd; d++) acc += xs[d] * key_w[(size_t)d * IKk + ik];
        g_k0[b * IKk + ik] = acc;
    }
}

// ---------------- stage A: q, scores, probs ----------------
__global__ void qscore_kernel(const float* __restrict__ hs,
                              const float* __restrict__ query_w,
                              const float* __restrict__ key_b) {
    int bu = blockIdx.x;
    int b = bu / Uu, u = bu % Uu;
    int ik = threadIdx.x; // 64
    __shared__ float hss[Hh];
    for (int i = ik; i < Hh; i += 64) hss[i] = hs[(size_t)bu * Hh + i];
    __syncthreads();
    const float* qw = query_w + (size_t)u * Hh * IKk;
    float q = 0.f;
    #pragma unroll 8
    for (int d = 0; d < Hh; d++) q += hss[d] * qw[(size_t)d * IKk + ik];
    float p0 = q * g_k0[b * IKk + ik];
    float p1 = q * key_b[ik];
    #pragma unroll
    for (int off = 16; off > 0; off >>= 1) {
        p0 += __shfl_down_sync(0xffffffffu, p0, off);
        p1 += __shfl_down_sync(0xffffffffu, p1, off);
    }
    __shared__ float r0[2], r1[2];
    if ((ik & 31) == 0) { r0[ik >> 5] = p0; r1[ik >> 5] = p1; }
    __syncthreads();
    if (ik == 0) {
        float s0 = (r0[0] + r0[1]) * 0.125f;   // / sqrt(64)
        float s1 = (r1[0] + r1[1]) * 0.125f;
        g_s0[bu] = s0;
        float m = fmaxf(s0, s1);
        float e0 = expf(s0 - m), e1 = expf(s1 - m);
        g_p0[bu] = e0 / (e0 + e1);
    }
}

// ---------------- top-k mask (jax.lax.top_k tie-break: lower index wins) -------
__global__ void topk_kernel() {
    int b = threadIdx.x; // 256 threads, 1 block
    float s[Uu];
    #pragma unroll
    for (int u = 0; u < Uu; u++) s[u] = g_s0[b * Uu + u];
    #pragma unroll
    for (int u = 0; u < Uu; u++) {
        int cnt = 0;
        #pragma unroll
        for (int t = 0; t < Uu; t++)
            if (s[t] > s[u] || (s[t] == s[u] && t < u)) cnt++;
        g_mask[b * Uu + u] = (cnt < Kk) ? 1.f : 0.f;
    }
}

// ---------------- inp = mask * (p0*v0 + (1-p0)*value_b) ----------------
__global__ void inp_kernel(const float* __restrict__ value_b) {
    int idx = blockIdx.x * blockDim.x + threadIdx.x;
    if (idx >= Bsz * Uu * IVv) return;
    int iv = idx % IVv;
    int bu = idx / IVv;
    int b = bu / Uu;
    float p0 = g_p0[bu];
    float v = p0 * g_v0[b * IVv + iv] + (1.f - p0) * value_b[iv];
    g_inp[idx] = g_mask[bu] * v;
}

// ---------------- generic per-u batched SGEMM (optionally dual-A/W summed) -----
// C[(b*U+u)*N + n] = sum_k A1[u*a1_uoff + b*a1_rs + k] * W1[u*K1*N + k*N + n]
//                  (+ same for A2/W2 if K2>0)
// mode 0: store into C.
// mode 1 (co epilogue, N must equal Hh): out = mask ? acc+ht : hs_in
__global__ void __launch_bounds__(256) gemm_bu(
    const float* __restrict__ A1, int a1_uoff, int a1_rs, const float* __restrict__ W1, int K1,
    const float* __restrict__ A2, int a2_uoff, int a2_rs, const float* __restrict__ W2, int K2,
    int N, float* __restrict__ C, int mode,
    const float* __restrict__ ht, const float* __restrict__ mk,
    const float* __restrict__ hs_in, float* __restrict__ outp)
{
    int u  = blockIdx.z;
    int n0 = blockIdx.x * 64, m0 = blockIdx.y * 64;
    __shared__ float As[16][65];
    __shared__ float Ws[16][64];
    float acc[4][4];
    #pragma unroll
    for (int i = 0; i < 4; i++)
        #pragma unroll
        for (int j = 0; j < 4; j++) acc[i][j] = 0.f;

    int tid = threadIdx.x;
    int tx = tid & 15, ty = tid >> 4;
    int wr = tid >> 6, wc = tid & 63;

    #pragma unroll
    for (int pass = 0; pass < 2; pass++) {
        const float* A = pass ? A2 : A1;
        const float* W = pass ? W2 : W1;
        int K   = pass ? K2 : K1;
        int uof = pass ? a2_uoff : a1_uoff;
        int ars = pass ? a2_rs : a1_rs;
        if (K == 0) continue;
        const float* Au = A + (size_t)u * uof;
        const float* Wu = W + (size_t)u * K * N;
        for (int k0 = 0; k0 < K; k0 += 16) {
            #pragma unroll
            for (int i = 0; i < 4; i++)
                As[tx][ty + 16 * i] = Au[(size_t)(m0 + ty + 16 * i) * ars + k0 + tx];
            #pragma unroll
            for (int i = 0; i < 4; i++)
                Ws[wr + 4 * i][wc] = Wu[(size_t)(k0 + wr + 4 * i) * N + n0 + wc];
            __syncthreads();
            #pragma unroll
            for (int kk = 0; kk < 16; kk++) {
                float af[4], wf[4];
                #pragma unroll
                for (int i = 0; i < 4; i++) af[i] = As[kk][ty + 16 * i];
                #pragma unroll
                for (int j = 0; j < 4; j++) wf[j] = Ws[kk][tx + 16 * j];
                #pragma unroll
                for (int i = 0; i < 4; i++)
                    #pragma unroll
                    for (int j = 0; j < 4; j++) acc[i][j] += af[i] * wf[j];
            }
            __syncthreads();
        }
    }

    #pragma unroll
    for (int i = 0; i < 4; i++) {
        int m  = m0 + ty + 16 * i;
        int bu = m * Uu + u;
        #pragma unroll
        for (int j = 0; j < 4; j++) {
            int n = n0 + tx + 16 * j;
            size_t idx = (size_t)bu * N + n;
            if (mode == 0) {
                C[idx] = acc[i][j];
            } else {
                float val = (mk[bu] != 0.f) ? (acc[i][j] + ht[idx]) : hs_in[idx];
                outp[idx] = val;
            }
        }
    }
}

// ---------------- LSTM gates + cs_new output ----------------
__global__ void gates_kernel(const float* __restrict__ cs, float* __restrict__ out_cs) {
    int idx = blockIdx.x * blockDim.x + threadIdx.x;
    if (idx >= Bsz * Uu * Hh) return;
    int h  = idx % Hh;
    int bu = idx / Hh;
    size_t base = (size_t)bu * 4 * Hh;
    float pi = g_pre[base + h];
    float pf = g_pre[base + Hh + h];
    float po = g_pre[base + 2 * Hh + h];
    float pg = g_pre[base + 3 * Hh + h];
    float it = 1.f / (1.f + expf(-pi));
    float ft = 1.f / (1.f + expf(-pf));
    float ot = 1.f / (1.f + expf(-po));
    float gt = tanhf(pg);
    float c  = cs[idx] * ft + it * gt;
    g_ct[idx] = c;
    g_ht[idx] = ot * tanhf(c);
    out_cs[idx] = (g_mask[bu] != 0.f) ? c : cs[idx];
}

// ---------------- communication attention: ctx[b,u,head*512+v] ----------------
__global__ void __launch_bounds__(256) attn_kernel() {
    int b = blockIdx.x >> 2;
    int head = blockIdx.x & 3;
    __shared__ float qcs[Uu][CKk + 1], kcs[Uu][CKk + 1], att[Uu][Uu];
    int tid = threadIdx.x;
    for (int i = tid; i < Uu * CKk; i += 256) {
        int uu = i / CKk, c = i % CKk;
        size_t base = (size_t)(b * Uu + uu) * (NCHh * CKk) + head * CKk + c;
        qcs[uu][c] = g_qc[base];
        kcs[uu][c] = g_kc[base];
    }
    __syncthreads();
    for (int i = tid; i < Uu * Uu; i += 256) {
        int uu = i / Uu, t = i % Uu;
        float s = 0.f;
        #pragma unroll
        for (int c = 0; c < CKk; c++) s += qcs[uu][c] * kcs[t][c];
        att[uu][t] = s * 0.17677669529663687f; // 1/sqrt(32)
    }
    __syncthreads();
    if (tid < Uu) {
        float m = -1e30f;
        #pragma unroll
        for (int t = 0; t < Uu; t++) m = fmaxf(m, att[tid][t]);
        float sum = 0.f;
        #pragma unroll
        for (int t = 0; t < Uu; t++) {
            float e = expf(att[tid][t] - m);
            att[tid][t] = e;
            sum += e;
        }
        float inv = 1.f / sum;
        #pragma unroll
        for (int t = 0; t < Uu; t++) att[tid][t] *= inv;
    }
    __syncthreads();
    // ctx: each thread owns 2 consecutive v, accumulates over all 24 u rows
    float accx[Uu], accy[Uu];
    #pragma unroll
    for (int uu = 0; uu < Uu; uu++) { accx[uu] = 0.f; accy[uu] = 0.f; }
    int v0 = tid * 2;
    #pragma unroll 4
    for (int t = 0; t < Uu; t++) {
        float2 vv = *(const float2*)&g_vc[(size_t)(b * Uu + t) * (NCHh * CVv) + head * CVv + v0];
        #pragma unroll
        for (int uu = 0; uu < Uu; uu++) {
            float a = att[uu][t];
            accx[uu] += a * vv.x;
            accy[uu] += a * vv.y;
        }
    }
    #pragma unroll
    for (int uu = 0; uu < Uu; uu++) {
        float2 o; o.x = accx[uu]; o.y = accy[uu];
        *(float2*)&g_ctx[(size_t)(b * Uu + uu) * (NCHh * CVv) + head * CVv + v0] = o;
    }
}

// ---------------- launch ----------------
extern "C" void kernel_launch(void* const* d_in, const int* in_sizes, int n_in,
                              void* d_out, int out_size) {
    const float* x       = (const float*)d_in[0];
    const float* hs      = (const float*)d_in[1];
    const float* cs      = (const float*)d_in[2];
    const float* key_w   = (const float*)d_in[3];
    const float* key_b   = (const float*)d_in[4];
    const float* value_w = (const float*)d_in[5];
    const float* value_b = (const float*)d_in[6];
    const float* query_w = (const float*)d_in[7];
    const float* i2h_w   = (const float*)d_in[8];
    const float* h2h_w   = (const float*)d_in[9];
    const float* qc_w    = (const float*)d_in[10];
    const float* kc_w    = (const float*)d_in[11];
    const float* vc_w    = (const float*)d_in[12];
    const float* co_w    = (const float*)d_in[13];
    float* out    = (float*)d_out;
    float* out_hs = out;
    float* out_cs = out + (size_t)Bsz * Uu * Hh;

    float *p_inp, *p_pre, *p_ht, *p_qc, *p_kc, *p_vc, *p_ctx, *p_mask;
    cudaGetSymbolAddress((void**)&p_inp,  g_inp);
    cudaGetSymbolAddress((void**)&p_pre,  g_pre);
    cudaGetSymbolAddress((void**)&p_ht,   g_ht);
    cudaGetSymbolAddress((void**)&p_qc,   g_qc);
    cudaGetSymbolAddress((void**)&p_kc,   g_kc);
    cudaGetSymbolAddress((void**)&p_vc,   g_vc);
    cudaGetSymbolAddress((void**)&p_ctx,  g_ctx);
    cudaGetSymbolAddress((void**)&p_mask, g_mask);

    kv_kernel<<<Bsz, 512>>>(x, key_w, key_b, value_w, value_b);
    qscore_kernel<<<Bsz * Uu, 64>>>(hs, query_w, key_b);
    topk_kernel<<<1, Bsz>>>();
    inp_kernel<<<(Bsz * Uu * IVv + 255) / 256, 256>>>(value_b);

    // preact = inp @ i2h_w[u] + hs @ h2h_w[u]   (M=256, N=2048, K=400+512, per u)
    {
        dim3 g(4 * Hh / 64, Bsz / 64, Uu);
        gemm_bu<<<g, 256>>>(p_inp, IVv, Uu * IVv, i2h_w, IVv,
                            hs,    Hh,  Uu * Hh,  h2h_w, Hh,
                            4 * Hh, p_pre, 0, nullptr, nullptr, nullptr, nullptr);
    }
    gates_kernel<<<(Bsz * Uu * Hh + 255) / 256, 256>>>(cs, out_cs);

    // qc / kc (N=128), vc (N=2048) from h_t
    {
        dim3 g(128 / 64, Bsz / 64, Uu);
        gemm_bu<<<g, 256>>>(p_ht, Hh, Uu * Hh, qc_w, Hh,
                            nullptr, 0, 0, nullptr, 0,
                            128, p_qc, 0, nullptr, nullptr, nullptr, nullptr);
        gemm_bu<<<g, 256>>>(p_ht, Hh, Uu * Hh, kc_w, Hh,
                            nullptr, 0, 0, nullptr, 0,
                            128, p_kc, 0, nullptr, nullptr, nullptr, nullptr);
    }
    {
        dim3 g(NCHh * CVv / 64, Bsz / 64, Uu);
        gemm_bu<<<g, 256>>>(p_ht, Hh, Uu * Hh, vc_w, Hh,
                            nullptr, 0, 0, nullptr, 0,
                            NCHh * CVv, p_vc, 0, nullptr, nullptr, nullptr, nullptr);
    }

    attn_kernel<<<Bsz * NCHh, 256>>>();

    // ctxo = ctx @ co_w[u]; hs_new = mask ? ctxo + h_t : hs   (fused epilogue)
    {
        dim3 g(Hh / 64, Bsz / 64, Uu);
        gemm_bu<<<g, 256>>>(p_ctx, NCHh * CVv, Uu * NCHh * CVv, co_w, NCHh * CVv,
                            nullptr, 0, 0, nullptr, 0,
                            Hh, nullptr, 1, p_ht, p_mask, hs, out_hs);
    }
}

// round 7
// speedup vs baseline: 1.0023x; 1.0023x over previous
#include <cuda_runtime.h>
#include <math.h>
#include <stddef.h>

#define Bsz 256
#define Dd  512
#define Hh  512
#define Uu  24
#define Kk  8
#define IKk 64
#define IVv 400
#define CKk 32
#define NCHh 4
#define CVv 512

// ---------------- scratch (static device globals; no allocation) ----------------
__device__ float g_k0[Bsz * IKk];
__device__ float g_v0[Bsz * IVv];
__device__ float g_s0[Bsz * Uu];
__device__ float g_p0[Bsz * Uu];
__device__ float g_mask[Bsz * Uu];
__device__ float g_inp[Bsz * Uu * IVv];
__device__ float g_pre[(size_t)Bsz * Uu * 4 * Hh];   // 50 MB
__device__ float g_ht[Bsz * Uu * Hh];
__device__ float g_ct[Bsz * Uu * Hh];
__device__ float g_qc[Bsz * Uu * NCHh * CKk];
__device__ float g_kc[Bsz * Uu * NCHh * CKk];
__device__ float g_vc[(size_t)Bsz * Uu * NCHh * CVv];  // 50 MB
__device__ float g_ctx[(size_t)Bsz * Uu * NCHh * CVv]; // 50 MB

// ---------------- stage A: k0 = x@key_w+key_b, v0 = x@value_w+value_b ----------
__global__ void kv_kernel(const float* __restrict__ x,
                          const float* __restrict__ key_w, const float* __restrict__ key_b,
                          const float* __restrict__ value_w, const float* __restrict__ value_b) {
    int b = blockIdx.x;
    __shared__ float xs[Dd];
    int tid = threadIdx.x; // 512
    xs[tid] = x[(size_t)b * Dd + tid];
    __syncthreads();
    if (tid < IVv) {
        float acc = value_b[tid];
        #pragma unroll 8
        for (int d = 0; d < Dd; d++) acc += xs[d] * value_w[(size_t)d * IVv + tid];
        g_v0[b * IVv + tid] = acc;
    } else if (tid < IVv + IKk) {
        int ik = tid - IVv;
        float acc = key_b[ik];
        #pragma unroll 8
        for (int d = 0; d < Dd; d++) acc += xs[d] * key_w[(size_t)d * IKk + ik];
        g_k0[b * IKk + ik] = acc;
    }
}

// ---------------- stage A: q, scores, probs ----------------
__global__ void qscore_kernel(const float* __restrict__ hs,
                              const float* __restrict__ query_w,
                              const float* __restrict__ key_b) {
    int bu = blockIdx.x;
    int b = bu / Uu, u = bu % Uu;
    int ik = threadIdx.x; // 64
    __shared__ float hss[Hh];
    for (int i = ik; i < Hh; i += 64) hss[i] = hs[(size_t)bu * Hh + i];
    __syncthreads();
    const float* qw = query_w + (size_t)u * Hh * IKk;
    float q = 0.f;
    #pragma unroll 8
    for (int d = 0; d < Hh; d++) q += hss[d] * qw[(size_t)d * IKk + ik];
    float p0 = q * g_k0[b * IKk + ik];
    float p1 = q * key_b[ik];
    #pragma unroll
    for (int off = 16; off > 0; off >>= 1) {
        p0 += __shfl_down_sync(0xffffffffu, p0, off);
        p1 += __shfl_down_sync(0xffffffffu, p1, off);
    }
    __shared__ float r0[2], r1[2];
    if ((ik & 31) == 0) { r0[ik >> 5] = p0; r1[ik >> 5] = p1; }
    __syncthreads();
    if (ik == 0) {
        float s0 = (r0[0] + r0[1]) * 0.125f;   // / sqrt(64)
        float s1 = (r1[0] + r1[1]) * 0.125f;
        g_s0[bu] = s0;
        float m = fmaxf(s0, s1);
        float e0 = expf(s0 - m), e1 = expf(s1 - m);
        g_p0[bu] = e0 / (e0 + e1);
    }
}

// ---------------- top-k mask (jax.lax.top_k tie-break: lower index wins) -------
__global__ void topk_kernel() {
    int b = threadIdx.x; // 256 threads, 1 block
    float s[Uu];
    #pragma unroll
    for (int u = 0; u < Uu; u++) s[u] = g_s0[b * Uu + u];
    #pragma unroll
    for (int u = 0; u < Uu; u++) {
        int cnt = 0;
        #pragma unroll
        for (int t = 0; t < Uu; t++)
            if (s[t] > s[u] || (s[t] == s[u] && t < u)) cnt++;
        g_mask[b * Uu + u] = (cnt < Kk) ? 1.f : 0.f;
    }
}

// ---------------- inp = mask * (p0*v0 + (1-p0)*value_b) ----------------
__global__ void inp_kernel(const float* __restrict__ value_b) {
    int idx = blockIdx.x * blockDim.x + threadIdx.x;
    if (idx >= Bsz * Uu * IVv) return;
    int iv = idx % IVv;
    int bu = idx / IVv;
    int b = bu / Uu;
    float p0 = g_p0[bu];
    float v = p0 * g_v0[b * IVv + iv] + (1.f - p0) * value_b[iv];
    g_inp[idx] = g_mask[bu] * v;
}

// ---------------- generic per-u batched SGEMM (optionally dual-A/W summed) -----
// C[(b*U+u)*N + n] = sum_k A1[u*a1_uoff + b*a1_rs + k] * W1[u*K1*N + k*N + n]
//                  (+ same for A2/W2 if K2>0)
// mode 0: store into C.
// mode 1 (co epilogue, N must equal Hh): out = mask ? acc+ht : hs_in
__global__ void __launch_bounds__(256) gemm_bu(
    const float* __restrict__ A1, int a1_uoff, int a1_rs, const float* __restrict__ W1, int K1,
    const float* __restrict__ A2, int a2_uoff, int a2_rs, const float* __restrict__ W2, int K2,
    int N, float* __restrict__ C, int mode,
    const float* __restrict__ ht, const float* __restrict__ mk,
    const float* __restrict__ hs_in, float* __restrict__ outp)
{
    int u  = blockIdx.z;
    int n0 = blockIdx.x * 64, m0 = blockIdx.y * 64;
    __shared__ float As[16][65];
    __shared__ float Ws[16][64];
    float acc[4][4];
    #pragma unroll
    for (int i = 0; i < 4; i++)
        #pragma unroll
        for (int j = 0; j < 4; j++) acc[i][j] = 0.f;

    int tid = threadIdx.x;
    int tx = tid & 15, ty = tid >> 4;
    int wr = tid >> 6, wc = tid & 63;

    #pragma unroll
    for (int pass = 0; pass < 2; pass++) {
        const float* A = pass ? A2 : A1;
        const float* W = pass ? W2 : W1;
        int K   = pass ? K2 : K1;
        int uof = pass ? a2_uoff : a1_uoff;
        int ars = pass ? a2_rs : a1_rs;
        if (K == 0) continue;
        const float* Au = A + (size_t)u * uof;
        const float* Wu = W + (size_t)u * K * N;
        for (int k0 = 0; k0 < K; k0 += 16) {
            #pragma unroll
            for (int i = 0; i < 4; i++)
                As[tx][ty + 16 * i] = Au[(size_t)(m0 + ty + 16 * i) * ars + k0 + tx];
            #pragma unroll
            for (int i = 0; i < 4; i++)
                Ws[wr + 4 * i][wc] = Wu[(size_t)(k0 + wr + 4 * i) * N + n0 + wc];
            __syncthreads();
            #pragma unroll
            for (int kk = 0; kk < 16; kk++) {
                float af[4], wf[4];
                #pragma unroll
                for (int i = 0; i < 4; i++) af[i] = As[kk][ty + 16 * i];
                #pragma unroll
                for (int j = 0; j < 4; j++) wf[j] = Ws[kk][tx + 16 * j];
                #pragma unroll
                for (int i = 0; i < 4; i++)
                    #pragma unroll
                    for (int j = 0; j < 4; j++) acc[i][j] += af[i] * wf[j];
            }
            __syncthreads();
        }
    }

    #pragma unroll
    for (int i = 0; i < 4; i++) {
        int m  = m0 + ty + 16 * i;
        int bu = m * Uu + u;
        #pragma unroll
        for (int j = 0; j < 4; j++) {
            int n = n0 + tx + 16 * j;
            size_t idx = (size_t)bu * N + n;
            if (mode == 0) {
                C[idx] = acc[i][j];
            } else {
                float val = (mk[bu] != 0.f) ? (acc[i][j] + ht[idx]) : hs_in[idx];
                outp[idx] = val;
            }
        }
    }
}

// ---------------- LSTM gates + cs_new output ----------------
__global__ void gates_kernel(const float* __restrict__ cs, float* __restrict__ out_cs) {
    int idx = blockIdx.x * blockDim.x + threadIdx.x;
    if (idx >= Bsz * Uu * Hh) return;
    int h  = idx % Hh;
    int bu = idx / Hh;
    size_t base = (size_t)bu * 4 * Hh;
    float pi = g_pre[base + h];
    float pf = g_pre[base + Hh + h];
    float po = g_pre[base + 2 * Hh + h];
    float pg = g_pre[base + 3 * Hh + h];
    float it = 1.f / (1.f + expf(-pi));
    float ft = 1.f / (1.f + expf(-pf));
    float ot = 1.f / (1.f + expf(-po));
    float gt = tanhf(pg);
    float c  = cs[idx] * ft + it * gt;
    g_ct[idx] = c;
    g_ht[idx] = ot * tanhf(c);
    out_cs[idx] = (g_mask[bu] != 0.f) ? c : cs[idx];
}

// ---------------- communication attention: ctx[b,u,head*512+v] ----------------
__global__ void __launch_bounds__(256) attn_kernel() {
    int b = blockIdx.x >> 2;
    int head = blockIdx.x & 3;
    __shared__ float qcs[Uu][CKk + 1], kcs[Uu][CKk + 1], att[Uu][Uu];
    int tid = threadIdx.x;
    for (int i = tid; i < Uu * CKk; i += 256) {
        int uu = i / CKk, c = i % CKk;
        size_t base = (size_t)(b * Uu + uu) * (NCHh * CKk) + head * CKk + c;
        qcs[uu][c] = g_qc[base];
        kcs[uu][c] = g_kc[base];
    }
    __syncthreads();
    for (int i = tid; i < Uu * Uu; i += 256) {
        int uu = i / Uu, t = i % Uu;
        float s = 0.f;
        #pragma unroll
        for (int c = 0; c < CKk; c++) s += qcs[uu][c] * kcs[t][c];
        att[uu][t] = s * 0.17677669529663687f; // 1/sqrt(32)
    }
    __syncthreads();
    if (tid < Uu) {
        float m = -1e30f;
        #pragma unroll
        for (int t = 0; t < Uu; t++) m = fmaxf(m, att[tid][t]);
        float sum = 0.f;
        #pragma unroll
        for (int t = 0; t < Uu; t++) {
            float e = expf(att[tid][t] - m);
            att[tid][t] = e;
            sum += e;
        }
        float inv = 1.f / sum;
        #pragma unroll
        for (int t = 0; t < Uu; t++) att[tid][t] *= inv;
    }
    __syncthreads();
    // ctx: each thread owns 2 consecutive v, accumulates over all 24 u rows
    float accx[Uu], accy[Uu];
    #pragma unroll
    for (int uu = 0; uu < Uu; uu++) { accx[uu] = 0.f; accy[uu] = 0.f; }
    int v0 = tid * 2;
    #pragma unroll 4
    for (int t = 0; t < Uu; t++) {
        float2 vv = *(const float2*)&g_vc[(size_t)(b * Uu + t) * (NCHh * CVv) + head * CVv + v0];
        #pragma unroll
        for (int uu = 0; uu < Uu; uu++) {
            float a = att[uu][t];
            accx[uu] += a * vv.x;
            accy[uu] += a * vv.y;
        }
    }
    #pragma unroll
    for (int uu = 0; uu < Uu; uu++) {
        float2 o; o.x = accx[uu]; o.y = accy[uu];
        *(float2*)&g_ctx[(size_t)(b * Uu + uu) * (NCHh * CVv) + head * CVv + v0] = o;
    }
}

// ---------------- launch ----------------
extern "C" void kernel_launch(void* const* d_in, const int* in_sizes, int n_in,
                              void* d_out, int out_size) {
    const float* x       = (const float*)d_in[0];
    const float* hs      = (const float*)d_in[1];
    const float* cs      = (const float*)d_in[2];
    const float* key_w   = (const float*)d_in[3];
    const float* key_b   = (const float*)d_in[4];
    const float* value_w = (const float*)d_in[5];
    const float* value_b = (const float*)d_in[6];
    const float* query_w = (const float*)d_in[7];
    const float* i2h_w   = (const float*)d_in[8];
    const float* h2h_w   = (const float*)d_in[9];
    const float* qc_w    = (const float*)d_in[10];
    const float* kc_w    = (const float*)d_in[11];
    const float* vc_w    = (const float*)d_in[12];
    const float* co_w    = (const float*)d_in[13];
    float* out    = (float*)d_out;
    float* out_hs = out;
    float* out_cs = out + (size_t)Bsz * Uu * Hh;

    float *p_inp, *p_pre, *p_ht, *p_qc, *p_kc, *p_vc, *p_ctx, *p_mask;
    cudaGetSymbolAddress((void**)&p_inp,  g_inp);
    cudaGetSymbolAddress((void**)&p_pre,  g_pre);
    cudaGetSymbolAddress((void**)&p_ht,   g_ht);
    cudaGetSymbolAddress((void**)&p_qc,   g_qc);
    cudaGetSymbolAddress((void**)&p_kc,   g_kc);
    cudaGetSymbolAddress((void**)&p_vc,   g_vc);
    cudaGetSymbolAddress((void**)&p_ctx,  g_ctx);
    cudaGetSymbolAddress((void**)&p_mask, g_mask);

    kv_kernel<<<Bsz, 512>>>(x, key_w, key_b, value_w, value_b);
    qscore_kernel<<<Bsz * Uu, 64>>>(hs, query_w, key_b);
    topk_kernel<<<1, Bsz>>>();
    inp_kernel<<<(Bsz * Uu * IVv + 255) / 256, 256>>>(value_b);

    // preact = inp @ i2h_w[u] + hs @ h2h_w[u]   (M=256, N=2048, K=400+512, per u)
    {
        dim3 g(4 * Hh / 64, Bsz / 64, Uu);
        gemm_bu<<<g, 256>>>(p_inp, IVv, Uu * IVv, i2h_w, IVv,
                            hs,    Hh,  Uu * Hh,  h2h_w, Hh,
                            4 * Hh, p_pre, 0, nullptr, nullptr, nullptr, nullptr);
    }
    gates_kernel<<<(Bsz * Uu * Hh + 255) / 256, 256>>>(cs, out_cs);

    // qc / kc (N=128), vc (N=2048) from h_t
    {
        dim3 g(128 / 64, Bsz / 64, Uu);
        gemm_bu<<<g, 256>>>(p_ht, Hh, Uu * Hh, qc_w, Hh,
                            nullptr, 0, 0, nullptr, 0,
                            128, p_qc, 0, nullptr, nullptr, nullptr, nullptr);
        gemm_bu<<<g, 256>>>(p_ht, Hh, Uu * Hh, kc_w, Hh,
                            nullptr, 0, 0, nullptr, 0,
                            128, p_kc, 0, nullptr, nullptr, nullptr, nullptr);
    }
    {
        dim3 g(NCHh * CVv / 64, Bsz / 64, Uu);
        gemm_bu<<<g, 256>>>(p_ht, Hh, Uu * Hh, vc_w, Hh,
                            nullptr, 0, 0, nullptr, 0,
                            NCHh * CVv, p_vc, 0, nullptr, nullptr, nullptr, nullptr);
    }

    attn_kernel<<<Bsz * NCHh, 256>>>();

    // ctxo = ctx @ co_w[u]; hs_new = mask ? ctxo + h_t : hs   (fused epilogue)
    {
        dim3 g(Hh / 64, Bsz / 64, Uu);
        gemm_bu<<<g, 256>>>(p_ctx, NCHh * CVv, Uu * NCHh * CVv, co_w, NCHh * CVv,
                            nullptr, 0, 0, nullptr, 0,
                            Hh, nullptr, 1, p_ht, p_mask, hs, out_hs);
    }
}

// round 8
// speedup vs baseline: 1.0781x; 1.0757x over previous
#include <cuda_runtime.h>
#include <math.h>
#include <stddef.h>

#define Bsz 256
#define Dd  512
#define Hh  512
#define Uu  24
#define Kk  8
#define IKk 64
#define IVv 400
#define CKk 32
#define NCHh 4
#define CVv 512

// ---------------- scratch (static device globals; no allocation) ----------------
__device__ float g_k0[Bsz * IKk];
__device__ float g_v0[Bsz * IVv];
__device__ float g_s0[Bsz * Uu];
__device__ float g_p0[Bsz * Uu];
__device__ float g_mask[Bsz * Uu];
__device__ float g_inp[Bsz * Uu * IVv];
__device__ float g_pre[(size_t)Bsz * Uu * 4 * Hh];   // 50 MB
__device__ float g_ht[Bsz * Uu * Hh];
__device__ float g_ct[Bsz * Uu * Hh];
__device__ float g_qc[Bsz * Uu * NCHh * CKk];
__device__ float g_kc[Bsz * Uu * NCHh * CKk];
__device__ float g_vc[(size_t)Bsz * Uu * NCHh * CVv];  // 50 MB
__device__ float g_ctx[(size_t)Bsz * Uu * NCHh * CVv]; // 50 MB

// ---------------- stage A: k0 = x@key_w+key_b, v0 = x@value_w+value_b ----------
__global__ void kv_kernel(const float* __restrict__ x,
                          const float* __restrict__ key_w, const float* __restrict__ key_b,
                          const float* __restrict__ value_w, const float* __restrict__ value_b) {
    int b = blockIdx.x;
    __shared__ float xs[Dd];
    int tid = threadIdx.x; // 512
    xs[tid] = x[(size_t)b * Dd + tid];
    __syncthreads();
    if (tid < IVv) {
        float acc = value_b[tid];
        #pragma unroll 8
        for (int d = 0; d < Dd; d++) acc += xs[d] * value_w[(size_t)d * IVv + tid];
        g_v0[b * IVv + tid] = acc;
    } else if (tid < IVv + IKk) {
        int ik = tid - IVv;
        float acc = key_b[ik];
        #pragma unroll 8
        for (int d = 0; d < Dd; d++) acc += xs[d] * key_w[(size_t)d * IKk + ik];
        g_k0[b * IKk + ik] = acc;
    }
}

// ---------------- stage A: q, scores, probs ----------------
__global__ void qscore_kernel(const float* __restrict__ hs,
                              const float* __restrict__ query_w,
                              const float* __restrict__ key_b) {
    int bu = blockIdx.x;
    int b = bu / Uu, u = bu % Uu;
    int ik = threadIdx.x; // 64
    __shared__ float hss[Hh];
    for (int i = ik; i < Hh; i += 64) hss[i] = hs[(size_t)bu * Hh + i];
    __syncthreads();
    const float* qw = query_w + (size_t)u * Hh * IKk;
    float q = 0.f;
    #pragma unroll 8
    for (int d = 0; d < Hh; d++) q += hss[d] * qw[(size_t)d * IKk + ik];
    float p0 = q * g_k0[b * IKk + ik];
    float p1 = q * key_b[ik];
    #pragma unroll
    for (int off = 16; off > 0; off >>= 1) {
        p0 += __shfl_down_sync(0xffffffffu, p0, off);
        p1 += __shfl_down_sync(0xffffffffu, p1, off);
    }
    __shared__ float r0[2], r1[2];
    if ((ik & 31) == 0) { r0[ik >> 5] = p0; r1[ik >> 5] = p1; }
    __syncthreads();
    if (ik == 0) {
        float s0 = (r0[0] + r0[1]) * 0.125f;   // / sqrt(64)
        float s1 = (r1[0] + r1[1]) * 0.125f;
        g_s0[bu] = s0;
        float m = fmaxf(s0, s1);
        float e0 = expf(s0 - m), e1 = expf(s1 - m);
        g_p0[bu] = e0 / (e0 + e1);
    }
}

// ---------------- top-k mask (jax.lax.top_k tie-break: lower index wins) -------
__global__ void topk_kernel() {
    int b = threadIdx.x; // 256 threads, 1 block
    float s[Uu];
    #pragma unroll
    for (int u = 0; u < Uu; u++) s[u] = g_s0[b * Uu + u];
    #pragma unroll
    for (int u = 0; u < Uu; u++) {
        int cnt = 0;
        #pragma unroll
        for (int t = 0; t < Uu; t++)
            if (s[t] > s[u] || (s[t] == s[u] && t < u)) cnt++;
        g_mask[b * Uu + u] = (cnt < Kk) ? 1.f : 0.f;
    }
}

// ---------------- inp = mask * (p0*v0 + (1-p0)*value_b) ----------------
__global__ void inp_kernel(const float* __restrict__ value_b) {
    int idx = blockIdx.x * blockDim.x + threadIdx.x;
    if (idx >= Bsz * Uu * IVv) return;
    int iv = idx % IVv;
    int bu = idx / IVv;
    int b = bu / Uu;
    float p0 = g_p0[bu];
    float v = p0 * g_v0[b * IVv + iv] + (1.f - p0) * value_b[iv];
    g_inp[idx] = g_mask[bu] * v;
}

// ===================== 128x128x16 double-buffered SGEMM =====================
// C[(b*U+u)*N + n] = sum_k A1[u*a1_uoff + b*a1_rs + k] * W1[u*K1*N + k*N + n]
//                  (+ same for A2/W2 if K2>0, mode != 2)
// mode 0: store into C.
// mode 1 (co epilogue, N==Hh): out = mask ? acc+ht : hs_in
// mode 2 (qk dual): grid.x selects (W1 -> C) vs (W2 -> C2), N == 128, single pass.
#define BM 128
#define BN 128
#define BKt 16

__global__ void __launch_bounds__(256) sgemm128(
    const float* __restrict__ A1, int a1_uoff, int a1_rs, const float* __restrict__ W1, int K1,
    const float* __restrict__ A2, int a2_uoff, int a2_rs, const float* __restrict__ W2, int K2,
    int N, float* __restrict__ C, int mode,
    float* __restrict__ C2,
    const float* __restrict__ ht, const float* __restrict__ mk,
    const float* __restrict__ hs_in, float* __restrict__ outp)
{
    __shared__ __align__(16) float As[2][BKt][BM];
    __shared__ __align__(16) float Ws[2][BKt][BN];

    int u  = blockIdx.z;
    int m0 = blockIdx.y * BM;
    int n0;
    const float* W1sel = W1;
    float* Csel = C;
    if (mode == 2) {
        n0 = 0;
        if (blockIdx.x) { W1sel = W2; Csel = C2; }
    } else {
        n0 = blockIdx.x * BN;
    }

    int tid = threadIdx.x;
    // A tile loading: 128 rows x 16 k; each thread: 2 float4
    int arow = tid >> 2;           // 0..63
    int acol = (tid & 3) * 4;      // 0,4,8,12
    // W tile loading: 16 k x 128 n; each thread: 2 float4
    int wrow = tid >> 5;           // 0..7
    int wcol = (tid & 31) * 4;     // 0..124
    // compute mapping: 16x16 threads, 8x8 micro-tile split as 4+4 with +64 offset
    int tx = (tid & 15) * 4;
    int ty = (tid >> 4) * 4;

    float acc[8][8];
    #pragma unroll
    for (int i = 0; i < 8; i++)
        #pragma unroll
        for (int j = 0; j < 8; j++) acc[i][j] = 0.f;

    #pragma unroll 1
    for (int pass = 0; pass < 2; pass++) {
        const float* A; const float* W; int K, uoff, ars;
        if (pass == 0) { A = A1; W = W1sel; K = K1; uoff = a1_uoff; ars = a1_rs; }
        else {
            if (mode == 2 || K2 == 0) break;
            A = A2; W = W2; K = K2; uoff = a2_uoff; ars = a2_rs;
        }
        const float* Au = A + (size_t)u * uoff;
        const float* Wu = W + (size_t)u * K * N;
        int T = K / BKt;

        float4 ra0, ra1, rw0, rw1;
        // prefetch tile 0
        ra0 = *(const float4*)&Au[(size_t)(m0 + arow) * ars + acol];
        ra1 = *(const float4*)&Au[(size_t)(m0 + arow + 64) * ars + acol];
        rw0 = *(const float4*)&Wu[(size_t)wrow * N + n0 + wcol];
        rw1 = *(const float4*)&Wu[(size_t)(wrow + 8) * N + n0 + wcol];
        // store into buffer 0
        As[0][acol + 0][arow] = ra0.x;
        As[0][acol + 1][arow] = ra0.y;
        As[0][acol + 2][arow] = ra0.z;
        As[0][acol + 3][arow] = ra0.w;
        As[0][acol + 0][arow + 64] = ra1.x;
        As[0][acol + 1][arow + 64] = ra1.y;
        As[0][acol + 2][arow + 64] = ra1.z;
        As[0][acol + 3][arow + 64] = ra1.w;
        *(float4*)&Ws[0][wrow][wcol]     = rw0;
        *(float4*)&Ws[0][wrow + 8][wcol] = rw1;
        __syncthreads();

        #pragma unroll 1
        for (int t = 0; t < T; t++) {
            int cur = t & 1, nxt = cur ^ 1;
            if (t + 1 < T) {
                int k0 = (t + 1) * BKt;
                ra0 = *(const float4*)&Au[(size_t)(m0 + arow) * ars + k0 + acol];
                ra1 = *(const float4*)&Au[(size_t)(m0 + arow + 64) * ars + k0 + acol];
                rw0 = *(const float4*)&Wu[(size_t)(k0 + wrow) * N + n0 + wcol];
                rw1 = *(const float4*)&Wu[(size_t)(k0 + wrow + 8) * N + n0 + wcol];
            }
            #pragma unroll
            for (int kk = 0; kk < BKt; kk++) {
                float a[8], w[8];
                *(float4*)&a[0] = *(const float4*)&As[cur][kk][ty];
                *(float4*)&a[4] = *(const float4*)&As[cur][kk][ty + 64];
                *(float4*)&w[0] = *(const float4*)&Ws[cur][kk][tx];
                *(float4*)&w[4] = *(const float4*)&Ws[cur][kk][tx + 64];
                #pragma unroll
                for (int i = 0; i < 8; i++)
                    #pragma unroll
                    for (int j = 0; j < 8; j++)
                        acc[i][j] += a[i] * w[j];
            }
            if (t + 1 < T) {
                As[nxt][acol + 0][arow] = ra0.x;
                As[nxt][acol + 1][arow] = ra0.y;
                As[nxt][acol + 2][arow] = ra0.z;
                As[nxt][acol + 3][arow] = ra0.w;
                As[nxt][acol + 0][arow + 64] = ra1.x;
                As[nxt][acol + 1][arow + 64] = ra1.y;
                As[nxt][acol + 2][arow + 64] = ra1.z;
                As[nxt][acol + 3][arow + 64] = ra1.w;
                *(float4*)&Ws[nxt][wrow][wcol]     = rw0;
                *(float4*)&Ws[nxt][wrow + 8][wcol] = rw1;
            }
            __syncthreads();
        }
    }

    // epilogue: rows (ty..ty+3, ty+64..ty+67), cols (tx..tx+3, tx+64..tx+67)
    #pragma unroll
    for (int ih = 0; ih < 2; ih++) {
        #pragma unroll
        for (int i = 0; i < 4; i++) {
            int m = m0 + ty + ih * 64 + i;
            int bu = m * Uu + u;
            size_t rowbase = (size_t)bu * N + n0;
            #pragma unroll
            for (int jh = 0; jh < 2; jh++) {
                int n = tx + jh * 64;
                float4 v;
                v.x = acc[ih * 4 + i][jh * 4 + 0];
                v.y = acc[ih * 4 + i][jh * 4 + 1];
                v.z = acc[ih * 4 + i][jh * 4 + 2];
                v.w = acc[ih * 4 + i][jh * 4 + 3];
                size_t idx = rowbase + n;
                if (mode == 1) {
                    if (mk[bu] != 0.f) {
                        float4 h = *(const float4*)&ht[idx];
                        v.x += h.x; v.y += h.y; v.z += h.z; v.w += h.w;
                    } else {
                        v = *(const float4*)&hs_in[idx];
                    }
                    *(float4*)&outp[idx] = v;
                } else {
                    *(float4*)&Csel[idx] = v;
                }
            }
        }
    }
}

// ---------------- LSTM gates + cs_new output ----------------
__global__ void gates_kernel(const float* __restrict__ cs, float* __restrict__ out_cs) {
    int idx = blockIdx.x * blockDim.x + threadIdx.x;
    if (idx >= Bsz * Uu * Hh) return;
    int h  = idx % Hh;
    int bu = idx / Hh;
    size_t base = (size_t)bu * 4 * Hh;
    float pi = g_pre[base + h];
    float pf = g_pre[base + Hh + h];
    float po = g_pre[base + 2 * Hh + h];
    float pg = g_pre[base + 3 * Hh + h];
    float it = 1.f / (1.f + expf(-pi));
    float ft = 1.f / (1.f + expf(-pf));
    float ot = 1.f / (1.f + expf(-po));
    float gt = tanhf(pg);
    float c  = cs[idx] * ft + it * gt;
    g_ct[idx] = c;
    g_ht[idx] = ot * tanhf(c);
    out_cs[idx] = (g_mask[bu] != 0.f) ? c : cs[idx];
}

// ---------------- communication attention: ctx[b,u,head*512+v] ----------------
__global__ void __launch_bounds__(256) attn_kernel() {
    int b = blockIdx.x >> 2;
    int head = blockIdx.x & 3;
    __shared__ float qcs[Uu][CKk + 1], kcs[Uu][CKk + 1], att[Uu][Uu];
    int tid = threadIdx.x;
    for (int i = tid; i < Uu * CKk; i += 256) {
        int uu = i / CKk, c = i % CKk;
        size_t base = (size_t)(b * Uu + uu) * (NCHh * CKk) + head * CKk + c;
        qcs[uu][c] = g_qc[base];
        kcs[uu][c] = g_kc[base];
    }
    __syncthreads();
    for (int i = tid; i < Uu * Uu; i += 256) {
        int uu = i / Uu, t = i % Uu;
        float s = 0.f;
        #pragma unroll
        for (int c = 0; c < CKk; c++) s += qcs[uu][c] * kcs[t][c];
        att[uu][t] = s * 0.17677669529663687f; // 1/sqrt(32)
    }
    __syncthreads();
    if (tid < Uu) {
        float m = -1e30f;
        #pragma unroll
        for (int t = 0; t < Uu; t++) m = fmaxf(m, att[tid][t]);
        float sum = 0.f;
        #pragma unroll
        for (int t = 0; t < Uu; t++) {
            float e = expf(att[tid][t] - m);
            att[tid][t] = e;
            sum += e;
        }
        float inv = 1.f / sum;
        #pragma unroll
        for (int t = 0; t < Uu; t++) att[tid][t] *= inv;
    }
    __syncthreads();
    float accx[Uu], accy[Uu];
    #pragma unroll
    for (int uu = 0; uu < Uu; uu++) { accx[uu] = 0.f; accy[uu] = 0.f; }
    int v0 = tid * 2;
    #pragma unroll 4
    for (int t = 0; t < Uu; t++) {
        float2 vv = *(const float2*)&g_vc[(size_t)(b * Uu + t) * (NCHh * CVv) + head * CVv + v0];
        #pragma unroll
        for (int uu = 0; uu < Uu; uu++) {
            float a = att[uu][t];
            accx[uu] += a * vv.x;
            accy[uu] += a * vv.y;
        }
    }
    #pragma unroll
    for (int uu = 0; uu < Uu; uu++) {
        float2 o; o.x = accx[uu]; o.y = accy[uu];
        *(float2*)&g_ctx[(size_t)(b * Uu + uu) * (NCHh * CVv) + head * CVv + v0] = o;
    }
}

// ---------------- launch ----------------
extern "C" void kernel_launch(void* const* d_in, const int* in_sizes, int n_in,
                              void* d_out, int out_size) {
    const float* x       = (const float*)d_in[0];
    const float* hs      = (const float*)d_in[1];
    const float* cs      = (const float*)d_in[2];
    const float* key_w   = (const float*)d_in[3];
    const float* key_b   = (const float*)d_in[4];
    const float* value_w = (const float*)d_in[5];
    const float* value_b = (const float*)d_in[6];
    const float* query_w = (const float*)d_in[7];
    const float* i2h_w   = (const float*)d_in[8];
    const float* h2h_w   = (const float*)d_in[9];
    const float* qc_w    = (const float*)d_in[10];
    const float* kc_w    = (const float*)d_in[11];
    const float* vc_w    = (const float*)d_in[12];
    const float* co_w    = (const float*)d_in[13];
    float* out    = (float*)d_out;
    float* out_hs = out;
    float* out_cs = out + (size_t)Bsz * Uu * Hh;

    float *p_inp, *p_pre, *p_ht, *p_qc, *p_kc, *p_vc, *p_ctx, *p_mask;
    cudaGetSymbolAddress((void**)&p_inp,  g_inp);
    cudaGetSymbolAddress((void**)&p_pre,  g_pre);
    cudaGetSymbolAddress((void**)&p_ht,   g_ht);
    cudaGetSymbolAddress((void**)&p_qc,   g_qc);
    cudaGetSymbolAddress((void**)&p_kc,   g_kc);
    cudaGetSymbolAddress((void**)&p_vc,   g_vc);
    cudaGetSymbolAddress((void**)&p_ctx,  g_ctx);
    cudaGetSymbolAddress((void**)&p_mask, g_mask);

    kv_kernel<<<Bsz, 512>>>(x, key_w, key_b, value_w, value_b);
    qscore_kernel<<<Bsz * Uu, 64>>>(hs, query_w, key_b);
    topk_kernel<<<1, Bsz>>>();
    inp_kernel<<<(Bsz * Uu * IVv + 255) / 256, 256>>>(value_b);

    // preact = inp @ i2h_w[u] + hs @ h2h_w[u]   (M=256, N=2048, K=400+512, per u)
    {
        dim3 g(4 * Hh / BN, Bsz / BM, Uu);
        sgemm128<<<g, 256>>>(p_inp, IVv, Uu * IVv, i2h_w, IVv,
                             hs,    Hh,  Uu * Hh,  h2h_w, Hh,
                             4 * Hh, p_pre, 0, nullptr,
                             nullptr, nullptr, nullptr, nullptr);
    }
    gates_kernel<<<(Bsz * Uu * Hh + 255) / 256, 256>>>(cs, out_cs);

    // qc & kc merged: one launch, grid.x selects weight/output (N=128 each)
    {
        dim3 g(2, Bsz / BM, Uu);
        sgemm128<<<g, 256>>>(p_ht, Hh, Uu * Hh, qc_w, Hh,
                             nullptr, 0, 0, kc_w, 0,
                             128, p_qc, 2, p_kc,
                             nullptr, nullptr, nullptr, nullptr);
    }
    // vc (N=2048) from h_t
    {
        dim3 g(NCHh * CVv / BN, Bsz / BM, Uu);
        sgemm128<<<g, 256>>>(p_ht, Hh, Uu * Hh, vc_w, Hh,
                             nullptr, 0, 0, nullptr, 0,
                             NCHh * CVv, p_vc, 0, nullptr,
                             nullptr, nullptr, nullptr, nullptr);
    }

    attn_kernel<<<Bsz * NCHh, 256>>>();

    // ctxo = ctx @ co_w[u]; hs_new = mask ? ctxo + h_t : hs   (fused epilogue)
    {
        dim3 g(Hh / BN, Bsz / BM, Uu);
        sgemm128<<<g, 256>>>(p_ctx, NCHh * CVv, Uu * NCHh * CVv, co_w, NCHh * CVv,
                             nullptr, 0, 0, nullptr, 0,
                             Hh, nullptr, 1, nullptr,
                             p_ht, p_mask, hs, out_hs);
    }
}